// round 13
// baseline (speedup 1.0000x reference)
#include <cuda_runtime.h>
#include <math.h>

#define Bb 2
#define Dd 192
#define Hh 56
#define Ww 56
#define Nn 16
#define Rr 12
#define Kk 4
#define LL (Hh*Ww)      /* 3136 */
#define LLP 3200        /* padded chain length for dz (prefetch overrun) */
#define TP 64           /* positions per prep tile */
#define CH 44           /* R + 2N */
#define CHP 48          /* padded channels */
#define PF 64           /* BC prefetch pad rows */
#define XSTR 196        /* xs smem row stride (words) */
#define DST2 52         /* transposed dblS row stride [p][c] */
#define ST 16           /* scan steps per tile */
#define NT (LL/ST)      /* 196 tiles */
#define NPREP 784
#define NSCAN 192

typedef unsigned long long u64;

// ---------------- device scratch ----------------
__device__ float2 g_dz[16*48*LLP*4];             // chunk-major (softplus, delta*u)
__device__ float2 g_BC[2*Bb*Kk*LL*16 + PF*16];   // per (row,no): {B_no,B_no+8},{C_no,C_no+8}
__device__ float  g_yk[16*48*LL*4];              // chunk-major scan outputs
__device__ float  g_xT[2*Bb*LL*Dd];
__device__ int    g_prep_cnt[8];

__device__ __forceinline__ float ex2(float x) {
    float r; asm("ex2.approx.ftz.f32 %0, %1;" : "=f"(r) : "f"(x)); return r;
}
__device__ __forceinline__ float lg2(float x) {
    float r; asm("lg2.approx.ftz.f32 %0, %1;" : "=f"(r) : "f"(x)); return r;
}
__device__ __forceinline__ u64 ffma2(u64 a, u64 b, u64 c) {
    u64 r; asm("fma.rn.f32x2 %0, %1, %2, %3;" : "=l"(r) : "l"(a), "l"(b), "l"(c)); return r;
}
__device__ __forceinline__ float hadd2(u64 v) {
    float lo, hi; asm("mov.b64 {%0, %1}, %2;" : "=f"(lo), "=f"(hi) : "l"(v)); return lo + hi;
}
#define LOG2E 1.44269504088896340736f
#define LN2   0.69314718055994530942f

__device__ __forceinline__ int tau_of(int k, int pos) {
    int t1 = (pos % Ww) * Hh + pos / Ww;
    switch (k) {
        case 0: return pos;
        case 1: return t1;
        case 2: return LL - 1 - pos;
        default: return LL - 1 - t1;
    }
}

__global__ void zero_cnt_kernel()
{
    if (threadIdx.x < 8) g_prep_cnt[threadIdx.x] = 0;
}

// ================= fused kernel: prep blocks + scan blocks =================
__global__ void __launch_bounds__(256, 2)
fused_kernel(const float* __restrict__ x1, const float* __restrict__ x2,
             const float* __restrict__ pw1, const float* __restrict__ pw2,
             const float* __restrict__ dtw1, const float* __restrict__ dtw2,
             const float* __restrict__ dtb1, const float* __restrict__ dtb2,
             const float* __restrict__ A1, const float* __restrict__ A2)
{
    extern __shared__ float sm[];
    const int bid = blockIdx.x;
    const int t   = threadIdx.x;

    if (bid < NPREP) {
        // ---------------- PREP ----------------
        const int g    = bid / 98;
        const int b    = g >> 2;
        const int k    = g & 3;
        const int rem  = bid - g*98;
        const int s    = rem / 49;
        const int pos0 = (rem - s*49) * TP;

        float* xs   = sm;                    // [TP][XSTR]
        float* Ws   = xs + TP*XSTR;          // [48][192]
        float* dtws = Ws + CHP*Dd;           // [192][12]
        float* bsm  = dtws + Dd*12;          // [192]
        float* dblS = bsm + Dd;              // [TP][DST2] transposed [p][c]

        const float* x   = s ? x2   : x1;
        const float* pw  = s ? pw2  : pw1;
        const float* dtw = s ? dtw2 : dtw1;
        const float* dtb = s ? dtb2 : dtb1;
        const int sb  = s*2 + b;
        const int sbo = (s^1)*2 + b;

        for (int e = t; e < Dd*(TP/4); e += 256) {
            int d = e >> 4, p4 = (e & 15) * 4;
            float4 v = *(const float4*)&x[(size_t)(b*Dd + d)*LL + pos0 + p4];
            xs[(p4+0)*XSTR + d] = v.x;
            xs[(p4+1)*XSTR + d] = v.y;
            xs[(p4+2)*XSTR + d] = v.z;
            xs[(p4+3)*XSTR + d] = v.w;
        }
        for (int e = t; e < CHP*Dd/4; e += 256) {
            float4 v = (e < CH*Dd/4) ? ((const float4*)pw)[(size_t)k*(CH*Dd/4) + e]
                                     : make_float4(0.f,0.f,0.f,0.f);
            ((float4*)Ws)[e] = v;
        }
        for (int e = t; e < Dd*Rr/4; e += 256)
            ((float4*)dtws)[e] = ((const float4*)dtw)[(size_t)k*(Dd*Rr/4) + e];
        if (t < Dd) bsm[t] = dtb[k*Dd + t];
        __syncthreads();

        if (k == 0) {
            for (int e = t; e < TP*Dd; e += 256) {
                int p = e / Dd, d = e - p*Dd;
                g_xT[(size_t)(sb*LL + pos0 + p)*Dd + d] = xs[p*XSTR + d];
            }
        }

        const int pg = t & 15;
        const int cb = t >> 4;

        {   // GEMM: dbl[c][p] = sum_d W[c][d] * x[d][p]; store transposed [p][c]
            u64 acc2[4][3];
            #pragma unroll
            for (int i = 0; i < 4; i++)
                #pragma unroll
                for (int j = 0; j < 3; j++) acc2[i][j] = 0ull;

            #pragma unroll 2
            for (int d4 = 0; d4 < Dd; d4 += 4) {
                ulonglong2 w0 = *(const ulonglong2*)&Ws[ cb      *Dd + d4];
                ulonglong2 w1 = *(const ulonglong2*)&Ws[(cb+16) *Dd + d4];
                ulonglong2 w2 = *(const ulonglong2*)&Ws[(cb+32) *Dd + d4];
                #pragma unroll
                for (int i = 0; i < 4; i++) {
                    ulonglong2 xv = *(const ulonglong2*)&xs[(pg + 16*i)*XSTR + d4];
                    acc2[i][0] = ffma2(xv.x, w0.x, acc2[i][0]);
                    acc2[i][0] = ffma2(xv.y, w0.y, acc2[i][0]);
                    acc2[i][1] = ffma2(xv.x, w1.x, acc2[i][1]);
                    acc2[i][1] = ffma2(xv.y, w1.y, acc2[i][1]);
                    acc2[i][2] = ffma2(xv.x, w2.x, acc2[i][2]);
                    acc2[i][2] = ffma2(xv.y, w2.y, acc2[i][2]);
                }
            }
            #pragma unroll
            for (int i = 0; i < 4; i++) {
                dblS[(pg + 16*i)*DST2 + cb     ] = hadd2(acc2[i][0]);
                dblS[(pg + 16*i)*DST2 + cb + 16] = hadd2(acc2[i][1]);
                dblS[(pg + 16*i)*DST2 + cb + 32] = hadd2(acc2[i][2]);
            }
        }
        __syncthreads();

        // packed B(own)/C(cross), traversal order, n-paired (no, no+8)
        for (int e = t; e < TP*8; e += 256) {
            int p = e >> 3, no = e & 7;
            int tauv = tau_of(k, pos0 + p);
            const float* row = &dblS[p*DST2];
            float2 bv = make_float2(row[12+no], row[20+no]);
            float2 cv = make_float2(row[28+no], row[36+no]);
            g_BC[((size_t)(sb *Kk + k)*LL + tauv)*16 + no*2    ] = bv;
            g_BC[((size_t)(sbo*Kk + k)*LL + tauv)*16 + no*2 + 1] = cv;
        }

        // dt epilogue: thread = (p, dq); dbl row cached in regs, dtws broadcast
        {
            const int p  = t & 63;
            const int dq = t >> 6;
            const size_t sbk48 = (size_t)(sb*Kk + k)*48;
            const int tauv = tau_of(k, pos0 + p);
            const float4 q0 = *(const float4*)&dblS[p*DST2 + 0];
            const float4 q1 = *(const float4*)&dblS[p*DST2 + 4];
            const float4 q2 = *(const float4*)&dblS[p*DST2 + 8];
            #pragma unroll 4
            for (int j = 0; j < 48; j++) {
                const int d = dq + 4*j;
                const float4* dw = (const float4*)&dtws[d*12];
                const float4 wa = dw[0], wb = dw[1], wc = dw[2];
                float a = bsm[d];
                a = fmaf(wa.x, q0.x, a); a = fmaf(wa.y, q0.y, a);
                a = fmaf(wa.z, q0.z, a); a = fmaf(wa.w, q0.w, a);
                a = fmaf(wb.x, q1.x, a); a = fmaf(wb.y, q1.y, a);
                a = fmaf(wb.z, q1.z, a); a = fmaf(wb.w, q1.w, a);
                a = fmaf(wc.x, q2.x, a); a = fmaf(wc.y, q2.y, a);
                a = fmaf(wc.z, q2.z, a); a = fmaf(wc.w, q2.w, a);
                float em = ex2(-fabsf(a) * LOG2E);
                float sp = fmaxf(a, 0.f) + lg2(1.f + em) * LN2;
                float z  = sp * xs[p*XSTR + d];
                g_dz[((sbk48 + j)*LLP + tauv)*4 + dq] = make_float2(sp, z);
            }
        }

        __threadfence();
        __syncthreads();
        if (t == 0) atomicAdd(&g_prep_cnt[g], 1);
        return;
    }

    // ---------------- SCAN ----------------
    {
        const int sid  = bid - NPREP;
        const int g    = sid / 24;
        const int b    = g >> 2;
        const int k    = g & 3;
        const int rem  = sid - g*24;
        const int s    = rem / 12;
        const int blk  = rem - s*12;
        const int sb   = s*2 + b;

        if (t == 0) {
            volatile int* c = (volatile int*)&g_prep_cnt[g];
            while (*c < 98) __nanosleep(128);
        }
        __syncthreads();
        __threadfence();

        float2* s_dz = (float2*)sm;            // [8 warps][4 slots][16 t][2]  8 KB
        float4* s_bc = (float4*)(sm + 2048);   // [8 warps][4 slots][128]     64 KB

        const int w    = t >> 5;
        const int lane = t & 31;
        const int dl = lane >> 4, n = lane & 15;
        const int dp = blk*16 + w*2;
        const int d  = dp + dl;

        const float* Alog = s ? A2 : A1;
        const float a = -__expf(Alog[(k*Dd + d)*Nn + n]) * LOG2E;
        const bool lo = (n < 8);
        const int no = n & 7;

        const size_t sbk48 = (size_t)(sb*Kk + k)*48;
        const int row0 = (sb*Kk + k)*LL;
        const int c0 = dp >> 2, droff = dp & 3;
        const float2* dz_src = g_dz + ((sbk48 + c0)*LLP)*4 + droff;   // step stride 4 float2
        const float4* bc_src = (const float4*)g_BC + (size_t)row0*8 + lane;
        float* yp = g_yk + ((sbk48 + c0)*(size_t)LL)*4 + (droff + dl);

        const int s0 = ((n & 1) << 3) | (((n >> 1) & 1) << 2) | (((n >> 2) & 1) << 1) | ((n >> 3) & 1);

        #define LOAD_TILE(slot, tile) do {                                                       \
            if (lane < 16) {                                                                     \
                unsigned za = (unsigned)__cvta_generic_to_shared(                                \
                    &s_dz[((w*4+(slot))*16 + lane)*2]);                                          \
                asm volatile("cp.async.cg.shared.global [%0], [%1], 16;" ::                      \
                             "r"(za), "l"(dz_src + (size_t)((tile)*ST + lane)*4));               \
            }                                                                                    \
            _Pragma("unroll")                                                                    \
            for (int q = 0; q < 4; q++) {                                                        \
                unsigned ba = (unsigned)__cvta_generic_to_shared(                                \
                    &s_bc[(w*4+(slot))*128 + q*32 + lane]);                                      \
                asm volatile("cp.async.cg.shared.global [%0], [%1], 16;" ::                      \
                             "r"(ba), "l"(bc_src + (size_t)(tile)*ST*8 + q*32));                 \
            }                                                                                    \
            asm volatile("cp.async.commit_group;");                                              \
        } while (0)

        LOAD_TILE(0, 0);
        LOAD_TILE(1, 1);
        LOAD_TILE(2, 2);

        float h = 0.f;
        for (int it = 0; it < NT; it++) {
            const int slot = it & 3;
            const int tt = it * ST;
            asm volatile("cp.async.wait_group 2;");
            __syncwarp();
            LOAD_TILE((it + 3) & 3, it + 3);

            float yy[16];
            #pragma unroll
            for (int hb = 0; hb < 2; hb++) {
                float2 dzr[8]; float4 bcr[8];
                #pragma unroll
                for (int j = 0; j < 8; j++) {
                    dzr[j] = s_dz[((w*4+slot)*16 + hb*8 + j)*2 + dl];
                    bcr[j] = s_bc[(w*4+slot)*128 + (hb*8 + j)*8 + no];
                }
                float e[8], Bn[8], Cn[8];
                #pragma unroll
                for (int j = 0; j < 8; j++) {
                    e[j]  = ex2(dzr[j].x * a);
                    Bn[j] = lo ? bcr[j].x : bcr[j].y;
                    Cn[j] = lo ? bcr[j].z : bcr[j].w;
                }
                #pragma unroll
                for (int j = 0; j < 8; j++) {
                    h = fmaf(e[j], h, dzr[j].y * Bn[j]);
                    yy[hb*8 + j] = h * Cn[j];
                }
            }
            // 4-round reduce-scatter over the 16 n-lanes (dl-halves are disjoint)
            #pragma unroll
            for (int j = 0; j < 8; j++) {
                float send = (n & 1) ? yy[j] : yy[8 + j];
                float recv = __shfl_xor_sync(0xffffffffu, send, 1);
                yy[j] = ((n & 1) ? yy[8 + j] : yy[j]) + recv;
            }
            #pragma unroll
            for (int j = 0; j < 4; j++) {
                float send = (n & 2) ? yy[j] : yy[4 + j];
                float recv = __shfl_xor_sync(0xffffffffu, send, 2);
                yy[j] = ((n & 2) ? yy[4 + j] : yy[j]) + recv;
            }
            #pragma unroll
            for (int j = 0; j < 2; j++) {
                float send = (n & 4) ? yy[j] : yy[2 + j];
                float recv = __shfl_xor_sync(0xffffffffu, send, 4);
                yy[j] = ((n & 4) ? yy[2 + j] : yy[j]) + recv;
            }
            {
                float send = (n & 8) ? yy[0] : yy[1];
                float recv = __shfl_xor_sync(0xffffffffu, send, 8);
                float y0 = ((n & 8) ? yy[1] : yy[0]) + recv;
                yp[(size_t)(tt + s0)*4] = y0;
            }
        }
        asm volatile("cp.async.wait_group 0;");
        #undef LOAD_TILE
    }
}

// ---------------- merge (sum k) + D*u + LayerNorm ----------------
__global__ void merge_ln_kernel(const float* __restrict__ D1s, const float* __restrict__ D2s,
                                const float* __restrict__ lnw, const float* __restrict__ lnb,
                                float* __restrict__ out)
{
    __shared__ float red[6];
    const int rid = blockIdx.x;
    const int sb = rid / LL, pos = rid % LL;
    const int s = sb >> 1;
    const int d = threadIdx.x;
    const float* Ds = s ? D2s : D1s;

    const int t1 = (pos % Ww) * Hh + pos / Ww;
    const size_t kb = (size_t)(sb*Kk)*48;
    const int dc = d >> 2, dr = d & 3;

    #define YIDX(KK, TT) (((kb + (KK)*48 + dc)*(size_t)LL + (TT))*4 + dr)
    float v = g_yk[YIDX(0, pos)]
            + g_yk[YIDX(1, t1)]
            + g_yk[YIDX(2, LL-1-pos)]
            + g_yk[YIDX(3, LL-1-t1)];
    #undef YIDX
    const float Dsum = Ds[d] + Ds[Dd + d] + Ds[2*Dd + d] + Ds[3*Dd + d];
    v = fmaf(Dsum, g_xT[(size_t)(sb*LL + pos)*Dd + d], v);

    float tsum = v;
    #pragma unroll
    for (int o = 16; o; o >>= 1) tsum += __shfl_xor_sync(0xffffffffu, tsum, o);
    if ((d & 31) == 0) red[d >> 5] = tsum;
    __syncthreads();
    const float mu = (red[0]+red[1]+red[2]+red[3]+red[4]+red[5]) * (1.f/192.f);
    const float dv = v - mu;
    __syncthreads();
    float q = dv*dv;
    #pragma unroll
    for (int o = 16; o; o >>= 1) q += __shfl_xor_sync(0xffffffffu, q, o);
    if ((d & 31) == 0) red[d >> 5] = q;
    __syncthreads();
    const float var = (red[0]+red[1]+red[2]+red[3]+red[4]+red[5]) * (1.f/192.f);

    out[rid*Dd + d] = dv * rsqrtf(var + 1e-5f) * lnw[d] + lnb[d];
}

// ---------------- launch ----------------
extern "C" void kernel_launch(void* const* d_in, const int* in_sizes, int n_in,
                              void* d_out, int out_size)
{
    const float* x1   = (const float*)d_in[0];
    const float* x2   = (const float*)d_in[1];
    const float* pw1  = (const float*)d_in[2];
    const float* pw2  = (const float*)d_in[3];
    const float* dtw1 = (const float*)d_in[4];
    const float* dtw2 = (const float*)d_in[5];
    const float* dtb1 = (const float*)d_in[6];
    const float* dtb2 = (const float*)d_in[7];
    const float* A1   = (const float*)d_in[8];
    const float* A2   = (const float*)d_in[9];
    const float* D1s  = (const float*)d_in[10];
    const float* D2s  = (const float*)d_in[11];
    const float* lnw  = (const float*)d_in[12];
    const float* lnb  = (const float*)d_in[13];
    float* out = (float*)d_out;

    const int smem = (TP*XSTR + CHP*Dd + Dd*12 + Dd + TP*DST2) * (int)sizeof(float); // 110,336 B
    cudaFuncSetAttribute(fused_kernel, cudaFuncAttributeMaxDynamicSharedMemorySize, smem);

    zero_cnt_kernel<<<1, 32>>>();
    fused_kernel<<<NPREP + NSCAN, 256, smem>>>(x1, x2, pw1, pw2, dtw1, dtw2,
                                               dtb1, dtb2, A1, A2);
    merge_ln_kernel<<<2*Bb*LL, Dd>>>(D1s, D2s, lnw, lnb, out);
}

// round 14
// speedup vs baseline: 1.5309x; 1.5309x over previous
#include <cuda_runtime.h>
#include <math.h>

#define Bb 2
#define Dd 192
#define Hh 56
#define Ww 56
#define Nn 16
#define Rr 12
#define Kk 4
#define LL (Hh*Ww)      /* 3136 */
#define LLP 3200        /* padded chain length for dz (prefetch overrun) */
#define TP 64           /* positions per prep tile */
#define CH 44           /* R + 2N */
#define CHP 48          /* padded channels */
#define PF 64           /* BC prefetch pad rows */
#define XSTR 196        /* xs smem row stride (words) */
#define DSTR 66         /* dblS row stride */
#define ST 16           /* scan steps per tile */
#define NT (LL/ST)      /* 196 tiles */
#define NPREP 784
#define NSCAN 192

typedef unsigned long long u64;

// ---------------- device scratch ----------------
__device__ float2 g_dz[16*48*LLP*4];             // chunk-major (softplus, delta*u)
__device__ float2 g_BC[2*Bb*Kk*LL*16 + PF*16];   // per (row,no): {B_no,B_no+8},{C_no,C_no+8}
__device__ float  g_yk[16*48*LL*4];              // chunk-major scan outputs
__device__ float  g_xT[2*Bb*LL*Dd];
__device__ int    g_prep_cnt[8];

__device__ __forceinline__ float ex2(float x) {
    float r; asm("ex2.approx.ftz.f32 %0, %1;" : "=f"(r) : "f"(x)); return r;
}
__device__ __forceinline__ float lg2(float x) {
    float r; asm("lg2.approx.ftz.f32 %0, %1;" : "=f"(r) : "f"(x)); return r;
}
__device__ __forceinline__ u64 ffma2(u64 a, u64 b, u64 c) {
    u64 r; asm("fma.rn.f32x2 %0, %1, %2, %3;" : "=l"(r) : "l"(a), "l"(b), "l"(c)); return r;
}
__device__ __forceinline__ float hadd2(u64 v) {
    float lo, hi; asm("mov.b64 {%0, %1}, %2;" : "=f"(lo), "=f"(hi) : "l"(v)); return lo + hi;
}
#define LOG2E 1.44269504088896340736f
#define LN2   0.69314718055994530942f

__device__ __forceinline__ int tau_of(int k, int pos) {
    int t1 = (pos % Ww) * Hh + pos / Ww;
    switch (k) {
        case 0: return pos;
        case 1: return t1;
        case 2: return LL - 1 - pos;
        default: return LL - 1 - t1;
    }
}

__global__ void zero_cnt_kernel()
{
    if (threadIdx.x < 8) g_prep_cnt[threadIdx.x] = 0;
}

// ================= fused kernel: prep blocks + scan blocks =================
__global__ void __launch_bounds__(256, 2)
fused_kernel(const float* __restrict__ x1, const float* __restrict__ x2,
             const float* __restrict__ pw1, const float* __restrict__ pw2,
             const float* __restrict__ dtw1, const float* __restrict__ dtw2,
             const float* __restrict__ dtb1, const float* __restrict__ dtb2,
             const float* __restrict__ A1, const float* __restrict__ A2)
{
    extern __shared__ float sm[];
    const int bid = blockIdx.x;
    const int t   = threadIdx.x;

    if (bid < NPREP) {
        // ---------------- PREP ----------------
        const int g    = bid / 98;
        const int b    = g >> 2;
        const int k    = g & 3;
        const int rem  = bid - g*98;
        const int s    = rem / 49;
        const int pos0 = (rem - s*49) * TP;

        float* xs   = sm;                    // [TP][XSTR]
        float* Ws   = xs + TP*XSTR;          // [48][192]
        float* dtws = Ws + CHP*Dd;           // [192][12]
        float* bsm  = dtws + Dd*12;          // [192]
        float* dblS = bsm + Dd;              // [48][DSTR]

        const float* x   = s ? x2   : x1;
        const float* pw  = s ? pw2  : pw1;
        const float* dtw = s ? dtw2 : dtw1;
        const float* dtb = s ? dtb2 : dtb1;
        const int sb  = s*2 + b;
        const int sbo = (s^1)*2 + b;

        for (int e = t; e < Dd*(TP/4); e += 256) {
            int d = e >> 4, p4 = (e & 15) * 4;
            float4 v = *(const float4*)&x[(size_t)(b*Dd + d)*LL + pos0 + p4];
            xs[(p4+0)*XSTR + d] = v.x;
            xs[(p4+1)*XSTR + d] = v.y;
            xs[(p4+2)*XSTR + d] = v.z;
            xs[(p4+3)*XSTR + d] = v.w;
        }
        for (int e = t; e < CHP*Dd/4; e += 256) {
            float4 v = (e < CH*Dd/4) ? ((const float4*)pw)[(size_t)k*(CH*Dd/4) + e]
                                     : make_float4(0.f,0.f,0.f,0.f);
            ((float4*)Ws)[e] = v;
        }
        for (int e = t; e < Dd*Rr/4; e += 256)
            ((float4*)dtws)[e] = ((const float4*)dtw)[(size_t)k*(Dd*Rr/4) + e];
        if (t < Dd) bsm[t] = dtb[k*Dd + t];
        __syncthreads();

        if (k == 0) {
            for (int e = t; e < TP*Dd; e += 256) {
                int p = e / Dd, d = e - p*Dd;
                g_xT[(size_t)(sb*LL + pos0 + p)*Dd + d] = xs[p*XSTR + d];
            }
        }

        const int pg = t & 15;
        const int cb = t >> 4;

        {   // GEMM: dbl[c][p] = sum_d W[c][d] * x[d][p]; 4 pos x 3 ch, f32x2 packed
            u64 acc2[4][3];
            #pragma unroll
            for (int i = 0; i < 4; i++)
                #pragma unroll
                for (int j = 0; j < 3; j++) acc2[i][j] = 0ull;

            #pragma unroll 2
            for (int d4 = 0; d4 < Dd; d4 += 4) {
                ulonglong2 w0 = *(const ulonglong2*)&Ws[ cb      *Dd + d4];
                ulonglong2 w1 = *(const ulonglong2*)&Ws[(cb+16) *Dd + d4];
                ulonglong2 w2 = *(const ulonglong2*)&Ws[(cb+32) *Dd + d4];
                #pragma unroll
                for (int i = 0; i < 4; i++) {
                    ulonglong2 xv = *(const ulonglong2*)&xs[(pg + 16*i)*XSTR + d4];
                    acc2[i][0] = ffma2(xv.x, w0.x, acc2[i][0]);
                    acc2[i][0] = ffma2(xv.y, w0.y, acc2[i][0]);
                    acc2[i][1] = ffma2(xv.x, w1.x, acc2[i][1]);
                    acc2[i][1] = ffma2(xv.y, w1.y, acc2[i][1]);
                    acc2[i][2] = ffma2(xv.x, w2.x, acc2[i][2]);
                    acc2[i][2] = ffma2(xv.y, w2.y, acc2[i][2]);
                }
            }
            #pragma unroll
            for (int i = 0; i < 4; i++) {
                dblS[ cb     *DSTR + pg + 16*i] = hadd2(acc2[i][0]);
                dblS[(cb+16) *DSTR + pg + 16*i] = hadd2(acc2[i][1]);
                dblS[(cb+32) *DSTR + pg + 16*i] = hadd2(acc2[i][2]);
            }
        }
        __syncthreads();

        // packed B(own)/C(cross), traversal order, n-paired (no, no+8)
        for (int e = t; e < TP*8; e += 256) {
            int p = e >> 3, no = e & 7;
            int tauv = tau_of(k, pos0 + p);
            float2 bv = make_float2(dblS[(12+no)*DSTR+p], dblS[(20+no)*DSTR+p]);
            float2 cv = make_float2(dblS[(28+no)*DSTR+p], dblS[(36+no)*DSTR+p]);
            g_BC[((size_t)(sb *Kk + k)*LL + tauv)*16 + no*2    ] = bv;
            g_BC[((size_t)(sbo*Kk + k)*LL + tauv)*16 + no*2 + 1] = cv;
        }

        // ---- dt epilogue: warp-uniform d (broadcast dtw), coalesced STG.128 dz ----
        {
            const int w    = t >> 5;
            const int lane = t & 31;
            const size_t sbk48 = (size_t)(sb*Kk + k)*48;
            #pragma unroll
            for (int cc = 0; cc < 6; cc++) {
                const int c  = w + cc*8;          // d-chunk handled by this warp
                const int d0 = c*4;
                #pragma unroll
                for (int ph = 0; ph < 2; ph++) {
                    const int p = ph*32 + lane;
                    const int tauv = tau_of(k, pos0 + p);
                    float rr[12];
                    #pragma unroll
                    for (int r = 0; r < 12; r++) rr[r] = dblS[r*DSTR + p];
                    float o8[8];
                    #pragma unroll
                    for (int q = 0; q < 4; q++) {
                        const int d = d0 + q;
                        const float4* dwp = (const float4*)&dtws[d*12];
                        const float4 wa = dwp[0], wb = dwp[1], wc = dwp[2];
                        float a = bsm[d];
                        a = fmaf(wa.x, rr[0], a);  a = fmaf(wa.y, rr[1], a);
                        a = fmaf(wa.z, rr[2], a);  a = fmaf(wa.w, rr[3], a);
                        a = fmaf(wb.x, rr[4], a);  a = fmaf(wb.y, rr[5], a);
                        a = fmaf(wb.z, rr[6], a);  a = fmaf(wb.w, rr[7], a);
                        a = fmaf(wc.x, rr[8], a);  a = fmaf(wc.y, rr[9], a);
                        a = fmaf(wc.z, rr[10], a); a = fmaf(wc.w, rr[11], a);
                        float em = ex2(-fabsf(a) * LOG2E);
                        float sp = fmaxf(a, 0.f) + lg2(1.f + em) * LN2;
                        float z  = sp * xs[p*XSTR + d];
                        o8[q*2] = sp; o8[q*2+1] = z;
                    }
                    float4* dst = (float4*)&g_dz[((sbk48 + c)*LLP + tauv)*4];
                    dst[0] = make_float4(o8[0], o8[1], o8[2], o8[3]);
                    dst[1] = make_float4(o8[4], o8[5], o8[6], o8[7]);
                }
            }
        }

        __threadfence();
        __syncthreads();
        if (t == 0) atomicAdd(&g_prep_cnt[g], 1);
        return;
    }

    // ---------------- SCAN (identical to R11) ----------------
    {
        const int sid  = bid - NPREP;
        const int g    = sid / 24;
        const int b    = g >> 2;
        const int k    = g & 3;
        const int rem  = sid - g*24;
        const int s    = rem / 12;
        const int chunk= rem - s*12;
        const int sb   = s*2 + b;

        if (t == 0) {
            volatile int* c = (volatile int*)&g_prep_cnt[g];
            while (*c < 98) __nanosleep(128);
        }
        __syncthreads();
        __threadfence();
        if (t >= 128) return;

        float2* s_dz = (float2*)sm;           // [4 warps][4 slots][64]   8 KB
        float4* s_bc = (float4*)(sm + 2048);  // [4 warps][4 slots][128] 32 KB

        const int w    = t >> 5;
        const int lane = t & 31;
        const int dl = lane >> 3, no = lane & 7;
        const int d0 = chunk*16 + w*4;
        const int d  = d0 + dl;

        const float* Alog = s ? A2 : A1;
        const float a0 = -__expf(Alog[(k*Dd + d)*Nn + no    ]) * LOG2E;
        const float a1 = -__expf(Alog[(k*Dd + d)*Nn + no + 8]) * LOG2E;

        const int row0 = (sb*Kk + k)*LL;
        const size_t chn = (size_t)(sb*Kk + k)*48 + (d0 >> 2);
        const float2* dz_src = g_dz + chn*LLP*4 + lane*2;
        const float4* bc_src = (const float4*)g_BC + (size_t)row0*8 + lane;
        float* yp = g_yk + chn*(size_t)LL*4 + dl;

        const int s0 = ((no & 1) << 3) | ((no & 2) << 1) | ((no & 4) >> 1);

        #define LOAD_TILE(slot, tile) do {                                                     \
            unsigned za = (unsigned)__cvta_generic_to_shared(&s_dz[(w*4+(slot))*64 + 2*lane]); \
            asm volatile("cp.async.cg.shared.global [%0], [%1], 16;" ::                        \
                         "r"(za), "l"(dz_src + (size_t)(tile)*64));                            \
            _Pragma("unroll")                                                                  \
            for (int q = 0; q < 4; q++) {                                                      \
                unsigned ba = (unsigned)__cvta_generic_to_shared(                              \
                                  &s_bc[(w*4+(slot))*128 + q*32 + lane]);                      \
                asm volatile("cp.async.cg.shared.global [%0], [%1], 16;" ::                    \
                             "r"(ba), "l"(bc_src + (size_t)(tile)*ST*8 + q*32));               \
            }                                                                                  \
            asm volatile("cp.async.commit_group;");                                            \
        } while (0)

        LOAD_TILE(0, 0);
        LOAD_TILE(1, 1);
        LOAD_TILE(2, 2);

        float h0 = 0.f, h1 = 0.f;
        for (int it = 0; it < NT; it++) {
            const int slot = it & 3;
            const int tt = it * ST;
            asm volatile("cp.async.wait_group 2;");
            __syncwarp();
            LOAD_TILE((it + 3) & 3, it + 3);

            float yy[16];
            #pragma unroll
            for (int hb = 0; hb < 2; hb++) {
                float2 dzr[8]; float4 bcr[8];
                #pragma unroll
                for (int j = 0; j < 8; j++) {
                    dzr[j] = s_dz[(w*4+slot)*64 + (hb*8 + j)*4 + dl];
                    bcr[j] = s_bc[(w*4+slot)*128 + (hb*8 + j)*8 + no];
                }
                float e0[8], e1[8];
                #pragma unroll
                for (int j = 0; j < 8; j++) {
                    e0[j] = ex2(dzr[j].x * a0);
                    e1[j] = ex2(dzr[j].x * a1);
                }
                #pragma unroll
                for (int j = 0; j < 8; j++) {
                    h0 = fmaf(e0[j], h0, dzr[j].y * bcr[j].x);
                    h1 = fmaf(e1[j], h1, dzr[j].y * bcr[j].y);
                    yy[hb*8 + j] = fmaf(h1, bcr[j].w, h0 * bcr[j].z);
                }
            }
            #pragma unroll
            for (int j = 0; j < 8; j++) {
                float send = (no & 1) ? yy[j] : yy[8 + j];
                float recv = __shfl_xor_sync(0xffffffffu, send, 1);
                yy[j] = ((no & 1) ? yy[8 + j] : yy[j]) + recv;
            }
            #pragma unroll
            for (int j = 0; j < 4; j++) {
                float send = (no & 2) ? yy[j] : yy[4 + j];
                float recv = __shfl_xor_sync(0xffffffffu, send, 2);
                yy[j] = ((no & 2) ? yy[4 + j] : yy[j]) + recv;
            }
            #pragma unroll
            for (int j = 0; j < 2; j++) {
                float send = (no & 4) ? yy[j] : yy[2 + j];
                float recv = __shfl_xor_sync(0xffffffffu, send, 4);
                yy[j] = ((no & 4) ? yy[2 + j] : yy[j]) + recv;
            }
            yp[(size_t)(tt + s0    )*4] = yy[0];
            yp[(size_t)(tt + s0 + 1)*4] = yy[1];
        }
        asm volatile("cp.async.wait_group 0;");
        #undef LOAD_TILE
    }
}

// ---------------- merge (sum k) + D*u + LayerNorm ----------------
__global__ void merge_ln_kernel(const float* __restrict__ D1s, const float* __restrict__ D2s,
                                const float* __restrict__ lnw, const float* __restrict__ lnb,
                                float* __restrict__ out)
{
    __shared__ float red[6];
    const int rid = blockIdx.x;
    const int sb = rid / LL, pos = rid % LL;
    const int s = sb >> 1;
    const int d = threadIdx.x;
    const float* Ds = s ? D2s : D1s;

    const int t1 = (pos % Ww) * Hh + pos / Ww;
    const size_t kb = (size_t)(sb*Kk)*48;
    const int dc = d >> 2, dr = d & 3;

    #define YIDX(KK, TT) (((kb + (KK)*48 + dc)*(size_t)LL + (TT))*4 + dr)
    float v = g_yk[YIDX(0, pos)]
            + g_yk[YIDX(1, t1)]
            + g_yk[YIDX(2, LL-1-pos)]
            + g_yk[YIDX(3, LL-1-t1)];
    #undef YIDX
    const float Dsum = Ds[d] + Ds[Dd + d] + Ds[2*Dd + d] + Ds[3*Dd + d];
    v = fmaf(Dsum, g_xT[(size_t)(sb*LL + pos)*Dd + d], v);

    float tsum = v;
    #pragma unroll
    for (int o = 16; o; o >>= 1) tsum += __shfl_xor_sync(0xffffffffu, tsum, o);
    if ((d & 31) == 0) red[d >> 5] = tsum;
    __syncthreads();
    const float mu = (red[0]+red[1]+red[2]+red[3]+red[4]+red[5]) * (1.f/192.f);
    const float dv = v - mu;
    __syncthreads();
    float q = dv*dv;
    #pragma unroll
    for (int o = 16; o; o >>= 1) q += __shfl_xor_sync(0xffffffffu, q, o);
    if ((d & 31) == 0) red[d >> 5] = q;
    __syncthreads();
    const float var = (red[0]+red[1]+red[2]+red[3]+red[4]+red[5]) * (1.f/192.f);

    out[rid*Dd + d] = dv * rsqrtf(var + 1e-5f) * lnw[d] + lnb[d];
}

// ---------------- launch ----------------
extern "C" void kernel_launch(void* const* d_in, const int* in_sizes, int n_in,
                              void* d_out, int out_size)
{
    const float* x1   = (const float*)d_in[0];
    const float* x2   = (const float*)d_in[1];
    const float* pw1  = (const float*)d_in[2];
    const float* pw2  = (const float*)d_in[3];
    const float* dtw1 = (const float*)d_in[4];
    const float* dtw2 = (const float*)d_in[5];
    const float* dtb1 = (const float*)d_in[6];
    const float* dtb2 = (const float*)d_in[7];
    const float* A1   = (const float*)d_in[8];
    const float* A2   = (const float*)d_in[9];
    const float* D1s  = (const float*)d_in[10];
    const float* D2s  = (const float*)d_in[11];
    const float* lnw  = (const float*)d_in[12];
    const float* lnb  = (const float*)d_in[13];
    float* out = (float*)d_out;

    const int smem = (TP*XSTR + CHP*Dd + Dd*12 + Dd + CHP*DSTR) * (int)sizeof(float); // 109,696 B
    cudaFuncSetAttribute(fused_kernel, cudaFuncAttributeMaxDynamicSharedMemorySize, smem);

    zero_cnt_kernel<<<1, 32>>>();
    fused_kernel<<<NPREP + NSCAN, 256, smem>>>(x1, x2, pw1, pw2, dtw1, dtw2,
                                               dtb1, dtb2, A1, A2);
    merge_ln_kernel<<<2*Bb*LL, Dd>>>(D1s, D2s, lnw, lnb, out);
}